// round 1
// baseline (speedup 1.0000x reference)
#include <cuda_runtime.h>
#include <math.h>

#define DEV_INLINE __device__ __forceinline__

namespace cfg {
constexpr int N = 20000;
constexpr int E = 600000;
constexpr int D = 512;
constexpr int H = 8;
constexpr int HID = 1024;
constexpr int FIN = 536;   // D + 3*H

constexpr long OFF_ZATT = 0;
constexpr long OFF_ZMLP = OFF_ZATT + (long)N * D;
constexpr long OFF_Q    = OFF_ZMLP + (long)N * D;
constexpr long OFF_K    = OFF_Q    + (long)N * D;
constexpr long OFF_LOG  = OFF_K    + (long)N * D;        // E*H, reused for p
constexpr long OFF_MXU  = OFF_LOG  + (long)E * H;        // N*H (as unsigned)
constexpr long OFF_MX   = OFF_MXU  + (long)N * H;        // N*H
constexpr long OFF_DEN  = OFF_MX   + (long)N * H;        // N*H
constexpr long OFF_ATT  = OFF_DEN  + (long)N * H;        // N*H*3
constexpr long OFF_FIN  = OFF_ATT  + (long)N * H * 3;    // N*FIN
constexpr long OFF_H1   = OFF_FIN  + (long)N * FIN;      // N*HID (reused by forces)
constexpr long OFF_H2   = OFF_H1   + (long)N * HID;      // N*HID (reused by forces)
constexpr long TOTAL    = OFF_H2   + (long)N * HID;
}

__device__ float g_scratch[cfg::TOTAL];

DEV_INLINE float gelu_tanh(float x) {
    // JAX default gelu (approximate=True): 0.5*x*(1+tanh(sqrt(2/pi)*(x+0.044715x^3)))
    float x3 = x * x * x;
    float t = tanhf(0.7978845608028654f * (x + 0.044715f * x3));
    return 0.5f * x * (1.0f + t);
}

// monotonic float<->uint mapping for atomicMax on floats
DEV_INLINE unsigned f2u(float f) {
    unsigned u = __float_as_uint(f);
    return (u & 0x80000000u) ? ~u : (u | 0x80000000u);
}
DEV_INLINE float u2f(unsigned u) {
    return __uint_as_float((u & 0x80000000u) ? (u ^ 0x80000000u) : ~u);
}

// ---------------------------------------------------------------------------
// init accumulators (must run every launch: graph replays must be deterministic)
// ---------------------------------------------------------------------------
__global__ void init_kernel() {
    int i = blockIdx.x * blockDim.x + threadIdx.x;
    const unsigned NEG_INF_KEY = 0x007FFFFFu;  // f2u(-inf)
    if (i < cfg::N * cfg::H) {
        g_scratch[cfg::OFF_DEN + i] = 0.0f;
        reinterpret_cast<unsigned*>(g_scratch + cfg::OFF_MXU)[i] = NEG_INF_KEY;
    }
    if (i < cfg::N * cfg::H * 3) {
        g_scratch[cfg::OFF_ATT + i] = 0.0f;
    }
}

// ---------------------------------------------------------------------------
// Fused double LayerNorm: z_att and z_mlp from one mean/var pass
// one block (128 thr) per row of 512
// ---------------------------------------------------------------------------
__global__ __launch_bounds__(128) void ln_kernel(
    const float* __restrict__ x,
    const float* __restrict__ ga, const float* __restrict__ ba,
    const float* __restrict__ gm, const float* __restrict__ bm)
{
    int row = blockIdx.x;
    int t = threadIdx.x;
    const float* xr = x + (long)row * cfg::D;

    float v[4];
    float s = 0.f, ss = 0.f;
#pragma unroll
    for (int i = 0; i < 4; i++) {
        v[i] = xr[t + 128 * i];
        s += v[i];
        ss += v[i] * v[i];
    }
    __shared__ float sh[2][4];
#pragma unroll
    for (int o = 16; o > 0; o >>= 1) {
        s  += __shfl_down_sync(0xffffffffu, s, o);
        ss += __shfl_down_sync(0xffffffffu, ss, o);
    }
    if ((t & 31) == 0) { sh[0][t >> 5] = s; sh[1][t >> 5] = ss; }
    __syncthreads();
    if (t == 0) {
        float S  = sh[0][0] + sh[0][1] + sh[0][2] + sh[0][3];
        float SS = sh[1][0] + sh[1][1] + sh[1][2] + sh[1][3];
        float mean = S / cfg::D;
        float var  = SS / cfg::D - mean * mean;
        sh[0][0] = mean;
        sh[1][0] = rsqrtf(var + 1e-5f);
    }
    __syncthreads();
    float mean = sh[0][0], rstd = sh[1][0];
    float* zatt = g_scratch + cfg::OFF_ZATT + (long)row * cfg::D;
    float* zmlp = g_scratch + cfg::OFF_ZMLP + (long)row * cfg::D;
#pragma unroll
    for (int i = 0; i < 4; i++) {
        int c = t + 128 * i;
        float zn = (v[i] - mean) * rstd;
        zatt[c] = zn * ga[c] + ba[c];
        zmlp[c] = zn * gm[c] + bm[c];
    }
}

// ---------------------------------------------------------------------------
// Register-tiled SGEMM: C[M,Nc] = epilogue(A[M,K] @ B[K,Nc] + bias)
// MODE 0: + bias
// MODE 1: gelu(+bias)
// MODE 2: Res + gelu(+bias)
// BM=BN=128, BK=8, 256 threads, 8x8 per thread. K % 8 == 0, Nc % 128 == 0.
// ---------------------------------------------------------------------------
template <int MODE>
__global__ __launch_bounds__(256) void sgemm_kernel(
    long aOff, const float* __restrict__ B, const float* __restrict__ bias,
    long resOff, long cOff, int M, int Nc, int K)
{
    constexpr int BM = 128, BN = 128, BK = 8, TM = 8, TN = 8;
    const float* A = g_scratch + aOff;
    const float* Res = g_scratch + resOff;
    float* C = g_scratch + cOff;

    __shared__ float As[BK][BM];
    __shared__ float Bs[BK][BN];

    int tid = threadIdx.x;
    int row0 = blockIdx.y * BM;
    int col0 = blockIdx.x * BN;

    int aRow = tid >> 1;          // 0..127
    int aCol = (tid & 1) * 4;     // 0 or 4
    int bRow = tid >> 5;          // 0..7
    int bCol = (tid & 31) * 4;    // 0..124

    int tr = tid >> 4;            // 0..15
    int tc = tid & 15;            // 0..15

    float acc[TM][TN];
#pragma unroll
    for (int i = 0; i < TM; i++)
#pragma unroll
        for (int j = 0; j < TN; j++) acc[i][j] = 0.f;

    for (int k0 = 0; k0 < K; k0 += BK) {
        float4 a4;
        if (row0 + aRow < M)
            a4 = *reinterpret_cast<const float4*>(A + (long)(row0 + aRow) * K + k0 + aCol);
        else
            a4 = make_float4(0.f, 0.f, 0.f, 0.f);
        As[aCol + 0][aRow] = a4.x;
        As[aCol + 1][aRow] = a4.y;
        As[aCol + 2][aRow] = a4.z;
        As[aCol + 3][aRow] = a4.w;

        float4 b4 = *reinterpret_cast<const float4*>(B + (long)(k0 + bRow) * Nc + col0 + bCol);
        *reinterpret_cast<float4*>(&Bs[bRow][bCol]) = b4;
        __syncthreads();

#pragma unroll
        for (int kk = 0; kk < BK; kk++) {
            float ar[TM], br[TN];
#pragma unroll
            for (int i = 0; i < TM; i++) ar[i] = As[kk][tr * TM + i];
#pragma unroll
            for (int j = 0; j < TN; j++) br[j] = Bs[kk][tc * TN + j];
#pragma unroll
            for (int i = 0; i < TM; i++)
#pragma unroll
                for (int j = 0; j < TN; j++)
                    acc[i][j] = fmaf(ar[i], br[j], acc[i][j]);
        }
        __syncthreads();
    }

#pragma unroll
    for (int i = 0; i < TM; i++) {
        int r = row0 + tr * TM + i;
        if (r >= M) break;
#pragma unroll
        for (int j = 0; j < TN; j += 4) {
            int c = col0 + tc * TN + j;
            float4 o;
            float* po = &o.x;
#pragma unroll
            for (int jj = 0; jj < 4; jj++) {
                float v = acc[i][j + jj] + bias[c + jj];
                if (MODE >= 1) v = gelu_tanh(v);
                if (MODE == 2) v += Res[(long)r * Nc + c + jj];
                po[jj] = v;
            }
            *reinterpret_cast<float4*>(C + (long)r * Nc + c) = o;
        }
    }
}

// ---------------------------------------------------------------------------
// Edge logits: one warp per edge. lane l covers dims [16l,16l+16) (head l/4).
// logits[e,h] = dot(q[row],k[col]) over head h * SCALE + att_bias[e]
// and atomicMax into segment max.
// ---------------------------------------------------------------------------
__global__ __launch_bounds__(256) void edge_logits_kernel(
    const int* __restrict__ ei, const float* __restrict__ att_bias)
{
    long gtid = (long)blockIdx.x * blockDim.x + threadIdx.x;
    long e = gtid >> 5;
    if (e >= cfg::E) return;
    int lane = threadIdx.x & 31;
    int r = ei[e];
    int c = ei[cfg::E + e];

    const float4* qr = reinterpret_cast<const float4*>(g_scratch + cfg::OFF_Q + (long)r * cfg::D) + lane * 4;
    const float4* kr = reinterpret_cast<const float4*>(g_scratch + cfg::OFF_K + (long)c * cfg::D) + lane * 4;
    float s = 0.f;
#pragma unroll
    for (int i = 0; i < 4; i++) {
        float4 a = qr[i], b = kr[i];
        s += a.x * b.x + a.y * b.y + a.z * b.z + a.w * b.w;
    }
    s += __shfl_xor_sync(0xffffffffu, s, 1);
    s += __shfl_xor_sync(0xffffffffu, s, 2);
    if ((lane & 3) == 0) {
        int h = lane >> 2;
        float lg = s * 0.125f + att_bias[e];
        g_scratch[cfg::OFF_LOG + e * cfg::H + h] = lg;
        atomicMax(&reinterpret_cast<unsigned*>(g_scratch + cfg::OFF_MXU)[r * cfg::H + h], f2u(lg));
    }
}

__global__ void finalize_mx_kernel() {
    int i = blockIdx.x * blockDim.x + threadIdx.x;
    if (i >= cfg::N * cfg::H) return;
    float v = u2f(reinterpret_cast<unsigned*>(g_scratch + cfg::OFF_MXU)[i]);
    g_scratch[cfg::OFF_MX + i] = isfinite(v) ? v : 0.0f;
}

// p = exp(logit - mx[row]); denom[row] += p  (p written in place of logits)
__global__ __launch_bounds__(256) void edge_exp_kernel(const int* __restrict__ ei) {
    long e = (long)blockIdx.x * blockDim.x + threadIdx.x;
    if (e >= cfg::E) return;
    int r = ei[e];
#pragma unroll
    for (int h = 0; h < cfg::H; h++) {
        float p = expf(g_scratch[cfg::OFF_LOG + e * cfg::H + h] - g_scratch[cfg::OFF_MX + r * cfg::H + h]);
        g_scratch[cfg::OFF_LOG + e * cfg::H + h] = p;
        atomicAdd(&g_scratch[cfg::OFF_DEN + r * cfg::H + h], p);
    }
}

// att[row,h,:] += (p/denom) * pos[col]
__global__ __launch_bounds__(256) void edge_contrib_kernel(
    const int* __restrict__ ei, const float* __restrict__ pos)
{
    long e = (long)blockIdx.x * blockDim.x + threadIdx.x;
    if (e >= cfg::E) return;
    int r = ei[e];
    int c = ei[cfg::E + e];
    float px = pos[(long)c * 3 + 0];
    float py = pos[(long)c * 3 + 1];
    float pz = pos[(long)c * 3 + 2];
#pragma unroll
    for (int h = 0; h < cfg::H; h++) {
        float w = g_scratch[cfg::OFF_LOG + e * cfg::H + h] /
                  g_scratch[cfg::OFF_DEN + r * cfg::H + h];
        atomicAdd(&g_scratch[cfg::OFF_ATT + (long)r * 24 + h * 3 + 0], w * px);
        atomicAdd(&g_scratch[cfg::OFF_ATT + (long)r * 24 + h * 3 + 1], w * py);
        atomicAdd(&g_scratch[cfg::OFF_ATT + (long)r * 24 + h * 3 + 2], w * pz);
    }
}

// fin = concat(z_mlp, att - pos broadcast)  [N, 536]
__global__ void build_fin_kernel(const float* __restrict__ pos) {
    long i = (long)blockIdx.x * blockDim.x + threadIdx.x;
    if (i >= (long)cfg::N * cfg::FIN) return;
    int n = (int)(i / cfg::FIN);
    int c = (int)(i % cfg::FIN);
    float v;
    if (c < cfg::D) {
        v = g_scratch[cfg::OFF_ZMLP + (long)n * cfg::D + c];
    } else {
        int j = c - cfg::D;           // 0..23 = h*3 + axis
        v = g_scratch[cfg::OFF_ATT + (long)n * 24 + j] - pos[(long)n * 3 + (j % 3)];
    }
    g_scratch[cfg::OFF_FIN + i] = v;
}

// ---------------------------------------------------------------------------
// Output heads: per-row GEMV. energy: [1024 -> 1], forces: [1024 -> 3]
// ---------------------------------------------------------------------------
__global__ __launch_bounds__(256) void energy_out_kernel(
    const float* __restrict__ W, const float* __restrict__ b, float* __restrict__ out)
{
    int n = blockIdx.x;
    int t = threadIdx.x;
    const float* hr = g_scratch + cfg::OFF_H2 + (long)n * cfg::HID;
    float s = 0.f;
    for (int j = t; j < cfg::HID; j += 256) s += hr[j] * W[j];
    __shared__ float sh[8];
#pragma unroll
    for (int o = 16; o > 0; o >>= 1) s += __shfl_down_sync(0xffffffffu, s, o);
    if ((t & 31) == 0) sh[t >> 5] = s;
    __syncthreads();
    if (t == 0) {
        float tot = 0.f;
#pragma unroll
        for (int i = 0; i < 8; i++) tot += sh[i];
        out[n] = tot + b[0];
    }
}

__global__ __launch_bounds__(256) void forces_out_kernel(
    const float* __restrict__ W, const float* __restrict__ b, float* __restrict__ out)
{
    int n = blockIdx.x;
    int t = threadIdx.x;
    const float* hr = g_scratch + cfg::OFF_H2 + (long)n * cfg::HID;
    float s0 = 0.f, s1 = 0.f, s2 = 0.f;
    for (int j = t; j < cfg::HID; j += 256) {
        float hv = hr[j];
        s0 += hv * W[j * 3 + 0];
        s1 += hv * W[j * 3 + 1];
        s2 += hv * W[j * 3 + 2];
    }
    __shared__ float sh[3][8];
#pragma unroll
    for (int o = 16; o > 0; o >>= 1) {
        s0 += __shfl_down_sync(0xffffffffu, s0, o);
        s1 += __shfl_down_sync(0xffffffffu, s1, o);
        s2 += __shfl_down_sync(0xffffffffu, s2, o);
    }
    if ((t & 31) == 0) { sh[0][t >> 5] = s0; sh[1][t >> 5] = s1; sh[2][t >> 5] = s2; }
    __syncthreads();
    if (t == 0) {
        float t0 = 0.f, t1 = 0.f, t2 = 0.f;
#pragma unroll
        for (int i = 0; i < 8; i++) { t0 += sh[0][i]; t1 += sh[1][i]; t2 += sh[2][i]; }
        out[(long)cfg::N + (long)n * 3 + 0] = t0 + b[0];
        out[(long)cfg::N + (long)n * 3 + 1] = t1 + b[1];
        out[(long)cfg::N + (long)n * 3 + 2] = t2 + b[2];
    }
}

// ---------------------------------------------------------------------------
extern "C" void kernel_launch(void* const* d_in, const int* in_sizes, int n_in,
                              void* d_out, int out_size)
{
    const float* x        = (const float*)d_in[0];
    const int*   ei       = (const int*)  d_in[1];
    const float* att_bias = (const float*)d_in[2];
    const float* pos      = (const float*)d_in[3];
    // d_in[4] = batch (unused: single graph)
    const float* g_att  = (const float*)d_in[5];
    const float* b_att  = (const float*)d_in[6];
    const float* g_mlp  = (const float*)d_in[7];
    const float* b_mlp  = (const float*)d_in[8];
    const float* Wq     = (const float*)d_in[9];
    const float* bq     = (const float*)d_in[10];
    const float* Wk     = (const float*)d_in[11];
    const float* bk     = (const float*)d_in[12];
    const float* We_in  = (const float*)d_in[13];
    const float* be_in  = (const float*)d_in[14];
    const float* We_h   = (const float*)d_in[15];
    const float* be_h   = (const float*)d_in[16];
    const float* We_out = (const float*)d_in[17];
    const float* be_out = (const float*)d_in[18];
    const float* Wf_in  = (const float*)d_in[19];
    const float* bf_in  = (const float*)d_in[20];
    const float* Wf_h   = (const float*)d_in[21];
    const float* bf_h   = (const float*)d_in[22];
    const float* Wf_out = (const float*)d_in[23];
    const float* bf_out = (const float*)d_in[24];
    float* out = (float*)d_out;

    const int MB = (cfg::N + 127) / 128;   // 157 row blocks

    // reset accumulators (graph-replay determinism)
    init_kernel<<<(cfg::N * cfg::H * 3 + 255) / 256, 256>>>();

    // LayerNorms
    ln_kernel<<<cfg::N, 128>>>(x, g_att, b_att, g_mlp, b_mlp);

    // q/k projections
    sgemm_kernel<0><<<dim3(cfg::D / 128, MB), 256>>>(cfg::OFF_ZATT, Wq, bq, 0, cfg::OFF_Q, cfg::N, cfg::D, cfg::D);
    sgemm_kernel<0><<<dim3(cfg::D / 128, MB), 256>>>(cfg::OFF_ZATT, Wk, bk, 0, cfg::OFF_K, cfg::N, cfg::D, cfg::D);

    // edge attention
    long logit_threads = (long)cfg::E * 32;
    edge_logits_kernel<<<(unsigned)((logit_threads + 255) / 256), 256>>>(ei, att_bias);
    finalize_mx_kernel<<<(cfg::N * cfg::H + 255) / 256, 256>>>();
    edge_exp_kernel<<<(cfg::E + 255) / 256, 256>>>(ei);
    edge_contrib_kernel<<<(cfg::E + 255) / 256, 256>>>(ei, pos);
    build_fin_kernel<<<(unsigned)(((long)cfg::N * cfg::FIN + 255) / 256), 256>>>(pos);

    // energy MLP
    sgemm_kernel<1><<<dim3(cfg::HID / 128, MB), 256>>>(cfg::OFF_ZMLP, We_in, be_in, 0, cfg::OFF_H1, cfg::N, cfg::HID, cfg::D);
    sgemm_kernel<2><<<dim3(cfg::HID / 128, MB), 256>>>(cfg::OFF_H1, We_h, be_h, cfg::OFF_H1, cfg::OFF_H2, cfg::N, cfg::HID, cfg::HID);
    energy_out_kernel<<<cfg::N, 256>>>(We_out, be_out, out);

    // forces MLP (reuses H1/H2 scratch)
    sgemm_kernel<1><<<dim3(cfg::HID / 128, MB), 256>>>(cfg::OFF_FIN, Wf_in, bf_in, 0, cfg::OFF_H1, cfg::N, cfg::HID, cfg::FIN);
    sgemm_kernel<2><<<dim3(cfg::HID / 128, MB), 256>>>(cfg::OFF_H1, Wf_h, bf_h, cfg::OFF_H1, cfg::OFF_H2, cfg::N, cfg::HID, cfg::HID);
    forces_out_kernel<<<cfg::N, 256>>>(Wf_out, bf_out, out);
}

// round 3
// speedup vs baseline: 2.2977x; 2.2977x over previous
#include <cuda_runtime.h>
#include <cuda_bf16.h>
#include <math.h>
#include <stdint.h>

#define DEV_INLINE __device__ __forceinline__

namespace cfg {
constexpr int N = 20000;
constexpr int E = 600000;
constexpr int D = 512;
constexpr int H = 8;
constexpr int HID = 1024;
constexpr int FIN = 536;    // D + 3*H
constexpr int FINP = 576;   // FIN padded to multiple of 64

// ---- fp32 scratch offsets ----
constexpr long OFF_Q   = 0;                         // N*D
constexpr long OFF_K   = OFF_Q   + (long)N * D;     // N*D
constexpr long OFF_LOG = OFF_K   + (long)N * D;     // E*H (reused for p)
constexpr long OFF_MXU = OFF_LOG + (long)E * H;     // N*H (unsigned keys)
constexpr long OFF_MX  = OFF_MXU + (long)N * H;     // N*H
constexpr long OFF_DEN = OFF_MX  + (long)N * H;     // N*H
constexpr long OFF_ATT = OFF_DEN + (long)N * H;     // N*24
constexpr long OFF_H1  = OFF_ATT + (long)N * 24;    // N*HID
constexpr long OFF_H2  = OFF_H1  + (long)N * HID;   // N*HID
constexpr long FTOTAL  = OFF_H2  + (long)N * HID;

// ---- bf16 scratch offsets (element counts) ----
constexpr long B_ZATT_HI = 0;
constexpr long B_ZATT_LO = B_ZATT_HI + (long)N * D;
constexpr long B_ZMLP_HI = B_ZATT_LO + (long)N * D;
constexpr long B_ZMLP_LO = B_ZMLP_HI + (long)N * D;
constexpr long B_H1_HI   = B_ZMLP_LO + (long)N * D;
constexpr long B_H1_LO   = B_H1_HI   + (long)N * HID;
constexpr long B_FIN_HI  = B_H1_LO   + (long)N * HID;
constexpr long B_FIN_LO  = B_FIN_HI  + (long)N * FINP;
constexpr long B_WQ_HI   = B_FIN_LO  + (long)N * FINP;
constexpr long B_WQ_LO   = B_WQ_HI   + (long)D * D;
constexpr long B_WK_HI   = B_WQ_LO   + (long)D * D;
constexpr long B_WK_LO   = B_WK_HI   + (long)D * D;
constexpr long B_WEIN_HI = B_WK_LO   + (long)D * D;
constexpr long B_WEIN_LO = B_WEIN_HI + (long)HID * D;
constexpr long B_WEH_HI  = B_WEIN_LO + (long)HID * D;
constexpr long B_WEH_LO  = B_WEH_HI  + (long)HID * HID;
constexpr long B_WFIN_HI = B_WEH_LO  + (long)HID * HID;
constexpr long B_WFIN_LO = B_WFIN_HI + (long)HID * FINP;
constexpr long B_WFH_HI  = B_WFIN_LO + (long)HID * FINP;
constexpr long B_WFH_LO  = B_WFH_HI  + (long)HID * HID;
constexpr long BTOTAL    = B_WFH_LO  + (long)HID * HID;
}

__device__ float g_f[cfg::FTOTAL];
__device__ __nv_bfloat16 g_bf[cfg::BTOTAL];

// ===========================================================================
// helpers
// ===========================================================================
DEV_INLINE float gelu_tanh(float x) {
    float x3 = x * x * x;
    float t = tanhf(0.7978845608028654f * (x + 0.044715f * x3));
    return 0.5f * x * (1.0f + t);
}
DEV_INLINE void split_bf16(float v, __nv_bfloat16& h, __nv_bfloat16& l) {
    h = __float2bfloat16(v);
    l = __float2bfloat16(v - __bfloat162float(h));
}
DEV_INLINE unsigned f2u(float f) {
    unsigned u = __float_as_uint(f);
    return (u & 0x80000000u) ? ~u : (u | 0x80000000u);
}
DEV_INLINE float u2f(unsigned u) {
    return __uint_as_float((u & 0x80000000u) ? (u ^ 0x80000000u) : ~u);
}
DEV_INLINE uint32_t smem_u32(const void* p) {
    uint32_t a;
    asm("{ .reg .u64 t; cvta.to.shared.u64 t, %1; cvt.u32.u64 %0, t; }" : "=r"(a) : "l"(p));
    return a;
}
DEV_INLINE void cp16(uint32_t dst, const void* src, int szbytes) {
    asm volatile("cp.async.cg.shared.global [%0], [%1], 16, %2;\n" :: "r"(dst), "l"(src), "r"(szbytes));
}
DEV_INLINE void cp_commit() { asm volatile("cp.async.commit_group;\n"); }
template <int NN>
DEV_INLINE void cp_wait() { asm volatile("cp.async.wait_group %0;\n" :: "n"(NN) : "memory"); }

DEV_INLINE void ldsm_x4(uint32_t& r0, uint32_t& r1, uint32_t& r2, uint32_t& r3, uint32_t addr) {
    asm volatile("ldmatrix.sync.aligned.m8n8.x4.shared.b16 {%0,%1,%2,%3}, [%4];"
                 : "=r"(r0), "=r"(r1), "=r"(r2), "=r"(r3) : "r"(addr));
}
DEV_INLINE void mma16816(float* c, const uint32_t* a, const uint32_t* b) {
    asm volatile("mma.sync.aligned.m16n8k16.row.col.f32.bf16.bf16.f32 "
                 "{%0,%1,%2,%3}, {%4,%5,%6,%7}, {%8,%9}, {%0,%1,%2,%3};"
                 : "+f"(c[0]), "+f"(c[1]), "+f"(c[2]), "+f"(c[3])
                 : "r"(a[0]), "r"(a[1]), "r"(a[2]), "r"(a[3]), "r"(b[0]), "r"(b[1]));
}

// ===========================================================================
// split-bf16 HMMA GEMM: C[M,Nc] = epi(A[M,K] @ B^T[Nc,K] + bias)
// A = (aHi+aLo) bf16 [M,K]; B = (bHi+bLo) bf16 [Nc,K] (weights transposed).
// acc = AhBh + AhBl + AlBh  (fp32 accum)
// MODE 0: C fp32 = acc+bias
// MODE 1: g=gelu(acc+bias); C fp32 = g; also split-bf16 (oHi/oLo)
// MODE 2: C fp32 = Res + gelu(acc+bias)
// CTA tile 128x128, BK=32, 8 warps (4m x 2n), warp tile 32x64, 2-stage cp.async
// ===========================================================================
constexpr int PADK = 40;                      // 32 elems + 8 pad (80B row stride)
constexpr int MAT_BYTES = 128 * PADK * 2;     // 10240 per matrix
constexpr int STG_BYTES = 4 * MAT_BYTES;      // 40960 per stage
constexpr int GEMM_SMEM = 2 * STG_BYTES;      // 81920

template <int MODE>
__global__ __launch_bounds__(256) void tc_gemm(
    long aHi, long aLo, long bHi, long bLo,
    const float* __restrict__ bias,
    long resOff, long cOff, long oHi, long oLo,
    int M, int Nc, int K)
{
    extern __shared__ char smem[];
    const uint32_t sb = smem_u32(smem);
    const int tid = threadIdx.x;
    const int wid = tid >> 5;
    const int lane = tid & 31;
    const int row0 = blockIdx.y * 128;
    const int col0 = blockIdx.x * 128;
    const int wm = wid & 3;        // 0..3 : 32-row band
    const int wn = wid >> 2;       // 0..1 : 64-col band

    const __nv_bfloat16* Ah = g_bf + aHi;
    const __nv_bfloat16* Al = g_bf + aLo;
    const __nv_bfloat16* Bh = g_bf + bHi;
    const __nv_bfloat16* Bl = g_bf + bLo;

    const int nChunks = K >> 5;

    // stage loader: 4 matrices x 128 rows x 64B (4 x16B segs)
    auto load_stage = [&](int stage, int chunk) {
        const long k0 = (long)chunk << 5;
        const uint32_t base = sb + stage * STG_BYTES;
#pragma unroll
        for (int j = 0; j < 2; j++) {
            int i = tid + j * 256;      // 0..511
            int r = i >> 2;
            int seg = i & 3;
            uint32_t so = r * 80 + seg * 16;
            bool va = (row0 + r) < M;
            long ar = va ? (long)(row0 + r) : 0;
            cp16(base + so,                 Ah + ar * K + k0 + seg * 8, va ? 16 : 0);
            cp16(base + MAT_BYTES + so,     Al + ar * K + k0 + seg * 8, va ? 16 : 0);
            long br = (long)(col0 + r);
            cp16(base + 2 * MAT_BYTES + so, Bh + br * K + k0 + seg * 8, 16);
            cp16(base + 3 * MAT_BYTES + so, Bl + br * K + k0 + seg * 8, 16);
        }
    };

    float acc[2][8][4];
#pragma unroll
    for (int mt = 0; mt < 2; mt++)
#pragma unroll
        for (int nt = 0; nt < 8; nt++)
#pragma unroll
            for (int q = 0; q < 4; q++) acc[mt][nt][q] = 0.f;

    // per-lane ldmatrix address offsets
    const int aRowOff = (lane & 7) + 8 * ((lane >> 3) & 1);   // + m
    const int aKbyte  = 16 * (lane >> 4);
    const int bRowOff = (lane & 7) + 8 * (lane >> 4);          // + n
    const int bKbyte  = 16 * ((lane >> 3) & 1);

    load_stage(0, 0);
    cp_commit();

    for (int c = 0; c < nChunks; c++) {
        if (c + 1 < nChunks) {
            load_stage((c + 1) & 1, c + 1);
            cp_commit();
            cp_wait<1>();
        } else {
            cp_wait<0>();
        }
        __syncthreads();

        const uint32_t st = sb + (c & 1) * STG_BYTES;
        const uint32_t baseAh = st;
        const uint32_t baseAl = st + MAT_BYTES;
        const uint32_t baseBh = st + 2 * MAT_BYTES;
        const uint32_t baseBl = st + 3 * MAT_BYTES;

#pragma unroll
        for (int kt = 0; kt < 2; kt++) {
            const int kb = kt * 32;   // byte offset of this k16 step
            uint32_t ah[2][4], al[2][4];
#pragma unroll
            for (int mt = 0; mt < 2; mt++) {
                uint32_t ro = (wm * 32 + mt * 16 + aRowOff) * 80 + kb + aKbyte;
                ldsm_x4(ah[mt][0], ah[mt][1], ah[mt][2], ah[mt][3], baseAh + ro);
                ldsm_x4(al[mt][0], al[mt][1], al[mt][2], al[mt][3], baseAl + ro);
            }
            uint32_t bh[8][2], bl[8][2];
#pragma unroll
            for (int nt2 = 0; nt2 < 4; nt2++) {
                uint32_t ro = (wn * 64 + nt2 * 16 + bRowOff) * 80 + kb + bKbyte;
                ldsm_x4(bh[2 * nt2][0], bh[2 * nt2][1], bh[2 * nt2 + 1][0], bh[2 * nt2 + 1][1], baseBh + ro);
                ldsm_x4(bl[2 * nt2][0], bl[2 * nt2][1], bl[2 * nt2 + 1][0], bl[2 * nt2 + 1][1], baseBl + ro);
            }
#pragma unroll
            for (int mt = 0; mt < 2; mt++)
#pragma unroll
                for (int nt = 0; nt < 8; nt++) {
                    mma16816(acc[mt][nt], ah[mt], bh[nt]);
                    mma16816(acc[mt][nt], ah[mt], bl[nt]);
                    mma16816(acc[mt][nt], al[mt], bh[nt]);
                }
        }
        __syncthreads();
    }

    // ---- epilogue straight from registers ----
    const int cRow = lane >> 2;          // 0..7
    const int cCol = 2 * (lane & 3);     // 0,2,4,6
#pragma unroll
    for (int mt = 0; mt < 2; mt++) {
#pragma unroll
        for (int half = 0; half < 2; half++) {    // c0/c1 vs c2/c3 (row +8)
            int r = row0 + wm * 32 + mt * 16 + cRow + half * 8;
            if (r >= M) continue;
#pragma unroll
            for (int nt = 0; nt < 8; nt++) {
                int n = col0 + wn * 64 + nt * 8 + cCol;
                float v0 = acc[mt][nt][half * 2 + 0] + bias[n];
                float v1 = acc[mt][nt][half * 2 + 1] + bias[n + 1];
                if (MODE >= 1) { v0 = gelu_tanh(v0); v1 = gelu_tanh(v1); }
                long gidx = (long)r * Nc + n;
                if (MODE == 2) {
                    float2 res = *reinterpret_cast<const float2*>(g_f + resOff + gidx);
                    v0 += res.x; v1 += res.y;
                }
                *reinterpret_cast<float2*>(g_f + cOff + gidx) = make_float2(v0, v1);
                if (MODE == 1) {
                    __nv_bfloat16 h0, l0, h1, l1;
                    split_bf16(v0, h0, l0);
                    split_bf16(v1, h1, l1);
                    __nv_bfloat162 hh; hh.x = h0; hh.y = h1;
                    __nv_bfloat162 ll; ll.x = l0; ll.y = l1;
                    *reinterpret_cast<__nv_bfloat162*>(g_bf + oHi + gidx) = hh;
                    *reinterpret_cast<__nv_bfloat162*>(g_bf + oLo + gidx) = ll;
                }
            }
        }
    }
}

// ===========================================================================
// weight conversion: W[K,Nc] fp32 -> (hi,lo) bf16 [Nc,Kpad] (transposed, padded)
// ===========================================================================
__global__ void conv_weight(const float* __restrict__ W, long dstHi, long dstLo,
                            int K, int Nc, int Kpad)
{
    long i = (long)blockIdx.x * blockDim.x + threadIdx.x;
    if (i >= (long)Nc * Kpad) return;
    int n = (int)(i / Kpad);
    int k = (int)(i % Kpad);
    float v = (k < K) ? W[(long)k * Nc + n] : 0.0f;
    __nv_bfloat16 h, l;
    split_bf16(v, h, l);
    g_bf[dstHi + i] = h;
    g_bf[dstLo + i] = l;
}

// ===========================================================================
__global__ void init_kernel() {
    int i = blockIdx.x * blockDim.x + threadIdx.x;
    const unsigned NEG_INF_KEY = 0x007FFFFFu;  // f2u(-inf)
    if (i < cfg::N * cfg::H) {
        g_f[cfg::OFF_DEN + i] = 0.0f;
        reinterpret_cast<unsigned*>(g_f + cfg::OFF_MXU)[i] = NEG_INF_KEY;
    }
    if (i < cfg::N * cfg::H * 3) {
        g_f[cfg::OFF_ATT + i] = 0.0f;
    }
}

// ===========================================================================
// double LayerNorm -> split bf16 activations
// ===========================================================================
__global__ __launch_bounds__(128) void ln_kernel(
    const float* __restrict__ x,
    const float* __restrict__ ga, const float* __restrict__ ba,
    const float* __restrict__ gm, const float* __restrict__ bm)
{
    int row = blockIdx.x;
    int t = threadIdx.x;
    const float* xr = x + (long)row * cfg::D;

    float v[4];
    float s = 0.f, ss = 0.f;
#pragma unroll
    for (int i = 0; i < 4; i++) {
        v[i] = xr[t + 128 * i];
        s += v[i];
        ss += v[i] * v[i];
    }
    __shared__ float sh[2][4];
#pragma unroll
    for (int o = 16; o > 0; o >>= 1) {
        s  += __shfl_down_sync(0xffffffffu, s, o);
        ss += __shfl_down_sync(0xffffffffu, ss, o);
    }
    if ((t & 31) == 0) { sh[0][t >> 5] = s; sh[1][t >> 5] = ss; }
    __syncthreads();
    if (t == 0) {
        float S  = sh[0][0] + sh[0][1] + sh[0][2] + sh[0][3];
        float SS = sh[1][0] + sh[1][1] + sh[1][2] + sh[1][3];
        float mean = S / cfg::D;
        float var  = SS / cfg::D - mean * mean;
        sh[0][0] = mean;
        sh[1][0] = rsqrtf(var + 1e-5f);
    }
    __syncthreads();
    float mean = sh[0][0], rstd = sh[1][0];
#pragma unroll
    for (int i = 0; i < 4; i++) {
        int c = t + 128 * i;
        float zn = (v[i] - mean) * rstd;
        float za = zn * ga[c] + ba[c];
        float zm = zn * gm[c] + bm[c];
        __nv_bfloat16 h, l;
        split_bf16(za, h, l);
        g_bf[cfg::B_ZATT_HI + (long)row * cfg::D + c] = h;
        g_bf[cfg::B_ZATT_LO + (long)row * cfg::D + c] = l;
        split_bf16(zm, h, l);
        g_bf[cfg::B_ZMLP_HI + (long)row * cfg::D + c] = h;
        g_bf[cfg::B_ZMLP_LO + (long)row * cfg::D + c] = l;
    }
}

// ===========================================================================
// edge attention
// ===========================================================================
__global__ __launch_bounds__(256) void edge_logits_kernel(
    const int* __restrict__ ei, const float* __restrict__ att_bias)
{
    long gtid = (long)blockIdx.x * blockDim.x + threadIdx.x;
    long e = gtid >> 5;
    if (e >= cfg::E) return;
    int lane = threadIdx.x & 31;
    int r = ei[e];
    int c = ei[cfg::E + e];

    const float4* qr = reinterpret_cast<const float4*>(g_f + cfg::OFF_Q + (long)r * cfg::D) + lane * 4;
    const float4* kr = reinterpret_cast<const float4*>(g_f + cfg::OFF_K + (long)c * cfg::D) + lane * 4;
    float s = 0.f;
#pragma unroll
    for (int i = 0; i < 4; i++) {
        float4 a = qr[i], b = kr[i];
        s += a.x * b.x + a.y * b.y + a.z * b.z + a.w * b.w;
    }
    s += __shfl_xor_sync(0xffffffffu, s, 1);
    s += __shfl_xor_sync(0xffffffffu, s, 2);
    if ((lane & 3) == 0) {
        int h = lane >> 2;
        float lg = s * 0.125f + att_bias[e];
        g_f[cfg::OFF_LOG + e * cfg::H + h] = lg;
        atomicMax(&reinterpret_cast<unsigned*>(g_f + cfg::OFF_MXU)[r * cfg::H + h], f2u(lg));
    }
}

__global__ void finalize_mx_kernel() {
    int i = blockIdx.x * blockDim.x + threadIdx.x;
    if (i >= cfg::N * cfg::H) return;
    float v = u2f(reinterpret_cast<unsigned*>(g_f + cfg::OFF_MXU)[i]);
    g_f[cfg::OFF_MX + i] = isfinite(v) ? v : 0.0f;
}

__global__ __launch_bounds__(256) void edge_exp_kernel(const int* __restrict__ ei) {
    long e = (long)blockIdx.x * blockDim.x + threadIdx.x;
    if (e >= cfg::E) return;
    int r = ei[e];
#pragma unroll
    for (int h = 0; h < cfg::H; h++) {
        float p = expf(g_f[cfg::OFF_LOG + e * cfg::H + h] - g_f[cfg::OFF_MX + r * cfg::H + h]);
        g_f[cfg::OFF_LOG + e * cfg::H + h] = p;
        atomicAdd(&g_f[cfg::OFF_DEN + r * cfg::H + h], p);
    }
}

__global__ __launch_bounds__(256) void edge_contrib_kernel(
    const int* __restrict__ ei, const float* __restrict__ pos)
{
    long e = (long)blockIdx.x * blockDim.x + threadIdx.x;
    if (e >= cfg::E) return;
    int r = ei[e];
    int c = ei[cfg::E + e];
    float px = pos[(long)c * 3 + 0];
    float py = pos[(long)c * 3 + 1];
    float pz = pos[(long)c * 3 + 2];
#pragma unroll
    for (int h = 0; h < cfg::H; h++) {
        float w = g_f[cfg::OFF_LOG + e * cfg::H + h] /
                  g_f[cfg::OFF_DEN + r * cfg::H + h];
        atomicAdd(&g_f[cfg::OFF_ATT + (long)r * 24 + h * 3 + 0], w * px);
        atomicAdd(&g_f[cfg::OFF_ATT + (long)r * 24 + h * 3 + 1], w * py);
        atomicAdd(&g_f[cfg::OFF_ATT + (long)r * 24 + h * 3 + 2], w * pz);
    }
}

// fin = concat(z_mlp, att - pos, zero-pad) as split bf16 [N, FINP]
__global__ void build_fin_kernel(const float* __restrict__ pos) {
    long i = (long)blockIdx.x * blockDim.x + threadIdx.x;
    if (i >= (long)cfg::N * cfg::FINP) return;
    int n = (int)(i / cfg::FINP);
    int c = (int)(i % cfg::FINP);
    __nv_bfloat16 h, l;
    if (c < cfg::D) {
        h = g_bf[cfg::B_ZMLP_HI + (long)n * cfg::D + c];
        l = g_bf[cfg::B_ZMLP_LO + (long)n * cfg::D + c];
    } else if (c < cfg::FIN) {
        int j = c - cfg::D;  // 0..23 = h*3 + axis
        float v = g_f[cfg::OFF_ATT + (long)n * 24 + j] - pos[(long)n * 3 + (j % 3)];
        split_bf16(v, h, l);
    } else {
        h = __float2bfloat16(0.f);
        l = __float2bfloat16(0.f);
    }
    g_bf[cfg::B_FIN_HI + i] = h;
    g_bf[cfg::B_FIN_LO + i] = l;
}

// ===========================================================================
// output heads
// ===========================================================================
__global__ __launch_bounds__(256) void energy_out_kernel(
    const float* __restrict__ W, const float* __restrict__ b, float* __restrict__ out)
{
    int n = blockIdx.x;
    int t = threadIdx.x;
    const float* hr = g_f + cfg::OFF_H2 + (long)n * cfg::HID;
    float s = 0.f;
    for (int j = t; j < cfg::HID; j += 256) s += hr[j] * W[j];
    __shared__ float sh[8];
#pragma unroll
    for (int o = 16; o > 0; o >>= 1) s += __shfl_down_sync(0xffffffffu, s, o);
    if ((t & 31) == 0) sh[t >> 5] = s;
    __syncthreads();
    if (t == 0) {
        float tot = 0.f;
#pragma unroll
        for (int i = 0; i < 8; i++) tot += sh[i];
        out[n] = tot + b[0];
    }
}

__global__ __launch_bounds__(256) void forces_out_kernel(
    const float* __restrict__ W, const float* __restrict__ b, float* __restrict__ out)
{
    int n = blockIdx.x;
    int t = threadIdx.x;
    const float* hr = g_f + cfg::OFF_H2 + (long)n * cfg::HID;
    float s0 = 0.f, s1 = 0.f, s2 = 0.f;
    for (int j = t; j < cfg::HID; j += 256) {
        float hv = hr[j];
        s0 += hv * W[j * 3 + 0];
        s1 += hv * W[j * 3 + 1];
        s2 += hv * W[j * 3 + 2];
    }
    __shared__ float sh[3][8];
#pragma unroll
    for (int o = 16; o > 0; o >>= 1) {
        s0 += __shfl_down_sync(0xffffffffu, s0, o);
        s1 += __shfl_down_sync(0xffffffffu, s1, o);
        s2 += __shfl_down_sync(0xffffffffu, s2, o);
    }
    if ((t & 31) == 0) { sh[0][t >> 5] = s0; sh[1][t >> 5] = s1; sh[2][t >> 5] = s2; }
    __syncthreads();
    if (t == 0) {
        float t0 = 0.f, t1 = 0.f, t2 = 0.f;
#pragma unroll
        for (int i = 0; i < 8; i++) { t0 += sh[0][i]; t1 += sh[1][i]; t2 += sh[2][i]; }
        out[(long)cfg::N + (long)n * 3 + 0] = t0 + b[0];
        out[(long)cfg::N + (long)n * 3 + 1] = t1 + b[1];
        out[(long)cfg::N + (long)n * 3 + 2] = t2 + b[2];
    }
}

// ===========================================================================
extern "C" void kernel_launch(void* const* d_in, const int* in_sizes, int n_in,
                              void* d_out, int out_size)
{
    const float* x        = (const float*)d_in[0];
    const int*   ei       = (const int*)  d_in[1];
    const float* att_bias = (const float*)d_in[2];
    const float* pos      = (const float*)d_in[3];
    const float* g_att  = (const float*)d_in[5];
    const float* b_att  = (const float*)d_in[6];
    const float* g_mlp  = (const float*)d_in[7];
    const float* b_mlp  = (const float*)d_in[8];
    const float* Wq     = (const float*)d_in[9];
    const float* bq     = (const float*)d_in[10];
    const float* Wk     = (const float*)d_in[11];
    const float* bk     = (const float*)d_in[12];
    const float* We_in  = (const float*)d_in[13];
    const float* be_in  = (const float*)d_in[14];
    const float* We_h   = (const float*)d_in[15];
    const float* be_h   = (const float*)d_in[16];
    const float* We_out = (const float*)d_in[17];
    const float* be_out = (const float*)d_in[18];
    const float* Wf_in  = (const float*)d_in[19];
    const float* bf_in  = (const float*)d_in[20];
    const float* Wf_h   = (const float*)d_in[21];
    const float* bf_h   = (const float*)d_in[22];
    const float* Wf_out = (const float*)d_in[23];
    const float* bf_out = (const float*)d_in[24];
    float* out = (float*)d_out;

    cudaFuncSetAttribute(tc_gemm<0>, cudaFuncAttributeMaxDynamicSharedMemorySize, GEMM_SMEM);
    cudaFuncSetAttribute(tc_gemm<1>, cudaFuncAttributeMaxDynamicSharedMemorySize, GEMM_SMEM);
    cudaFuncSetAttribute(tc_gemm<2>, cudaFuncAttributeMaxDynamicSharedMemorySize, GEMM_SMEM);

    const int MB = (cfg::N + 127) / 128;   // 157

    init_kernel<<<(cfg::N * cfg::H * 3 + 255) / 256, 256>>>();
    ln_kernel<<<cfg::N, 128>>>(x, g_att, b_att, g_mlp, b_mlp);

    // weight conversion (transpose + split)
    auto cw = [](const float* W, long dh, long dl, int K, int Nc, int Kpad) {
        long tot = (long)Nc * Kpad;
        conv_weight<<<(unsigned)((tot + 255) / 256), 256>>>(W, dh, dl, K, Nc, Kpad);
    };
    cw(Wq,    cfg::B_WQ_HI,   cfg::B_WQ_LO,   512, 512, 512);
    cw(Wk,    cfg::B_WK_HI,   cfg::B_WK_LO,   512, 512, 512);
    cw(We_in, cfg::B_WEIN_HI, cfg::B_WEIN_LO, 512, 1024, 512);
    cw(We_h,  cfg::B_WEH_HI,  cfg::B_WEH_LO,  1024, 1024, 1024);
    cw(Wf_in, cfg::B_WFIN_HI, cfg::B_WFIN_LO, 536, 1024, 576);
    cw(Wf_h,  cfg::B_WFH_HI,  cfg::B_WFH_LO,  1024, 1024, 1024);

    // q/k projections (tensor cores)
    tc_gemm<0><<<dim3(4, MB), 256, GEMM_SMEM>>>(cfg::B_ZATT_HI, cfg::B_ZATT_LO,
        cfg::B_WQ_HI, cfg::B_WQ_LO, bq, 0, cfg::OFF_Q, 0, 0, cfg::N, 512, 512);
    tc_gemm<0><<<dim3(4, MB), 256, GEMM_SMEM>>>(cfg::B_ZATT_HI, cfg::B_ZATT_LO,
        cfg::B_WK_HI, cfg::B_WK_LO, bk, 0, cfg::OFF_K, 0, 0, cfg::N, 512, 512);

    // edge attention
    long logit_threads = (long)cfg::E * 32;
    edge_logits_kernel<<<(unsigned)((logit_threads + 255) / 256), 256>>>(ei, att_bias);
    finalize_mx_kernel<<<(cfg::N * cfg::H + 255) / 256, 256>>>();
    edge_exp_kernel<<<(cfg::E + 255) / 256, 256>>>(ei);
    edge_contrib_kernel<<<(cfg::E + 255) / 256, 256>>>(ei, pos);
    build_fin_kernel<<<(unsigned)(((long)cfg::N * cfg::FINP + 255) / 256), 256>>>(pos);

    // energy MLP
    tc_gemm<1><<<dim3(8, MB), 256, GEMM_SMEM>>>(cfg::B_ZMLP_HI, cfg::B_ZMLP_LO,
        cfg::B_WEIN_HI, cfg::B_WEIN_LO, be_in, 0, cfg::OFF_H1,
        cfg::B_H1_HI, cfg::B_H1_LO, cfg::N, 1024, 512);
    tc_gemm<2><<<dim3(8, MB), 256, GEMM_SMEM>>>(cfg::B_H1_HI, cfg::B_H1_LO,
        cfg::B_WEH_HI, cfg::B_WEH_LO, be_h, cfg::OFF_H1, cfg::OFF_H2,
        0, 0, cfg::N, 1024, 1024);
    energy_out_kernel<<<cfg::N, 256>>>(We_out, be_out, out);

    // forces MLP
    tc_gemm<1><<<dim3(8, MB), 256, GEMM_SMEM>>>(cfg::B_FIN_HI, cfg::B_FIN_LO,
        cfg::B_WFIN_HI, cfg::B_WFIN_LO, bf_in, 0, cfg::OFF_H1,
        cfg::B_H1_HI, cfg::B_H1_LO, cfg::N, 1024, 576);
    tc_gemm<2><<<dim3(8, MB), 256, GEMM_SMEM>>>(cfg::B_H1_HI, cfg::B_H1_LO,
        cfg::B_WFH_HI, cfg::B_WFH_LO, bf_h, cfg::OFF_H1, cfg::OFF_H2,
        0, 0, cfg::N, 1024, 1024);
    forces_out_kernel<<<cfg::N, 256>>>(Wf_out, bf_out, out);
}